// round 12
// baseline (speedup 1.0000x reference)
#include <cuda_runtime.h>
#include <cstdint>

// MVRModel MaxSim, base sm_100 (no tcgen05 on this toolchain path).
//   B=16, Q=32, E=128, N=64 docs/batch, D=512 doc tokens.
//   score[b,n] = sum_q qmask[b,q] * max_d( dmask ? q·d : MASK ), MASK-max -> 0.
//
// R9: mask-aware row gather — dmask is ~Bernoulli(0.5), and masked doc tokens
// contribute MASKV regardless of their embeddings, so their 512B rows are never
// read. Compact valid token indices per doc (ballot+popc+smem atomic), then
// cp.async-gather only valid rows (512B contiguous each). Halves DRAM traffic.
// Compute structure = R7 (warp = m16 x n16, bq in regs, 3-buf pipeline); the
// dynamic chunk count uses one commit_group per iteration (empty when done) so
// wait_group stays the constant 2.

#define MASKV (-10000.0f)

static constexpr int BB = 16, QQ = 32, EE = 128, NN = 64, DD = 512;
static constexpr int CH = 32;                  // compacted tokens per chunk
static constexpr int RS = 132;                 // padded row stride (floats)
static constexpr int RSB = RS * 4;             // 528 B

static constexpr unsigned BUFB = 32u * RSB;            // 16896 per buffer
static constexpr unsigned OFF_LIST = 3 * BUFB;         // 512 u16 = 1024 B
static constexpr unsigned OFF_CNT  = OFF_LIST + 1024;  // int
static constexpr unsigned OFF_RED  = OFF_CNT + 64;     // 64 floats
static constexpr unsigned SMEM_BYTES = OFF_RED + 256;  // ~52.3KB -> 4 CTAs/SM

__device__ __forceinline__ uint32_t cvta_smem(const void* p) {
    uint32_t a;
    asm("{ .reg .u64 t; cvta.to.shared.u64 t, %1; cvt.u32.u64 %0, t; }" : "=r"(a) : "l"(p));
    return a;
}

__device__ __forceinline__ void cp16(uint32_t dst, const void* src) {
    asm volatile("cp.async.cg.shared.global [%0], [%1], 16;" :: "r"(dst), "l"(src) : "memory");
}

__device__ __forceinline__ void commit_group() {
    asm volatile("cp.async.commit_group;" ::: "memory");
}

__device__ __forceinline__ uint32_t to_tf32(float x) {
    uint32_t r;
    asm("cvt.rna.tf32.f32 %0, %1;" : "=r"(r) : "f"(x));
    return r;
}

// Gather one chunk of 32 compacted rows (512B each). 128 threads: 4 per row,
// thread covers float4 cols (t&3) + i*4 (64B contiguous per row-quad issue).
__device__ __forceinline__ void load_chunk_gather(uint32_t bufbase,
                                                  const float4* __restrict__ dg,
                                                  const uint16_t* __restrict__ list,
                                                  int c, int tid) {
    const int r = tid >> 2;               // 0..31 compacted row in chunk
    const int q = tid & 3;
    const int g = list[c * 32 + r];       // global token row (smem broadcast x4)
    const float4* src = dg + (size_t)g * 32;
    const uint32_t dst = bufbase + (uint32_t)r * RSB;
#pragma unroll
    for (int i = 0; i < 8; i++) {
        int j = q + i * 4;                // float4 col 0..31
        cp16(dst + (uint32_t)j * 16u, src + j);
    }
    commit_group();
}

// Compute one chunk: warp owns (m-tile mt: rows mt*16..+16) x (n-half nh).
__device__ __forceinline__ void compute_chunk(uint32_t buf, uint32_t a_lane_off,
                                              const uint32_t (&bq)[2][16][2],
                                              int dok0, int dok1, float (&rmax)[2][2]) {
    float acc[2][4];
#pragma unroll
    for (int nt = 0; nt < 2; nt++)
#pragma unroll
        for (int i = 0; i < 4; i++) acc[nt][i] = 0.0f;

#pragma unroll
    for (int ks = 0; ks < 16; ks++) {
        uint32_t a0, a1, a2, a3;
        asm volatile("ldmatrix.sync.aligned.m8n8.x4.shared.b16 {%0,%1,%2,%3}, [%4];"
                     : "=r"(a0), "=r"(a1), "=r"(a2), "=r"(a3)
                     : "r"(buf + a_lane_off + (uint32_t)ks * 32u));
        a0 = to_tf32(__uint_as_float(a0));
        a1 = to_tf32(__uint_as_float(a1));
        a2 = to_tf32(__uint_as_float(a2));
        a3 = to_tf32(__uint_as_float(a3));
#pragma unroll
        for (int nt = 0; nt < 2; nt++) {
            asm volatile(
                "mma.sync.aligned.m16n8k8.row.col.f32.tf32.tf32.f32 "
                "{%0,%1,%2,%3}, {%4,%5,%6,%7}, {%8,%9}, {%0,%1,%2,%3};"
                : "+f"(acc[nt][0]), "+f"(acc[nt][1]), "+f"(acc[nt][2]), "+f"(acc[nt][3])
                : "r"(a0), "r"(a1), "r"(a2), "r"(a3),
                  "r"(bq[nt][ks][0]), "r"(bq[nt][ks][1]));
        }
    }
    // acc[nt]: c0=(r,2c), c1=(r,2c+1), c2=(r+8,2c), c3=(r+8,2c+1); r=lane>>2, c=lane&3.
#pragma unroll
    for (int nt = 0; nt < 2; nt++) {
        float v0 = dok0 ? acc[nt][0] : MASKV;
        float v1 = dok0 ? acc[nt][1] : MASKV;
        float v2 = dok1 ? acc[nt][2] : MASKV;
        float v3 = dok1 ? acc[nt][3] : MASKV;
        rmax[nt][0] = fmaxf(rmax[nt][0], fmaxf(v0, v2));
        rmax[nt][1] = fmaxf(rmax[nt][1], fmaxf(v1, v3));
    }
}

__global__ void __launch_bounds__(128, 4)
mvr_maxsim_kernel(const float* __restrict__ qe, const int* __restrict__ qm,
                  const float* __restrict__ de, const int* __restrict__ dm,
                  float* __restrict__ out) {
    extern __shared__ char smem[];
    const uint32_t sb = cvta_smem(smem);
    uint16_t* list = (uint16_t*)(smem + OFF_LIST);
    int* cnt = (int*)(smem + OFF_CNT);
    float* red = (float*)(smem + OFF_RED);

    const int tid = threadIdx.x;
    const int wid = tid >> 5;
    const int lid = tid & 31;
    const int mt = wid & 1;               // m-tile (chunk rows mt*16..+16)
    const int nh = wid >> 1;              // n-half (q-cols nh*16..+16)
    const int doc = blockIdx.x;           // b*64 + n
    const int b = doc >> 6;

    // ---- Group 0: Q (32x128) into buf2 (transient) ----
    const float4* qg = (const float4*)(qe + (size_t)b * QQ * EE);
#pragma unroll
    for (int i = 0; i < 8; i++) {
        int idx = tid + i * 128;          // 0..1023
        int qrow = idx >> 5;
        int j = idx & 31;
        cp16(sb + 2 * BUFB + (uint32_t)qrow * RSB + (uint32_t)j * 16u, qg + idx);
    }
    commit_group();

    // ---- Compaction of valid doc-token indices (overlaps the Q load) ----
    if (tid == 0) *cnt = 0;
    __syncthreads();
#pragma unroll
    for (int i = 0; i < 4; i++) {
        int tok = wid * 128 + i * 32 + lid;
        int valid = dm[doc * DD + tok] != 0;
        unsigned m = __ballot_sync(0xFFFFFFFFu, valid);
        int base = 0;
        if (lid == 0) base = atomicAdd(cnt, __popc(m));
        base = __shfl_sync(0xFFFFFFFFu, base, 0);
        if (valid) list[base + __popc(m & ((1u << lid) - 1u))] = (uint16_t)tok;
    }
    __syncthreads();
    const int V = *cnt;                    // valid tokens, 0..512
    const int NC = (V + 31) >> 5;          // chunks of 32
    // pad list to a chunk multiple with index 0 (slots >= V are invalidated later)
    for (int s = V + tid; s < NC * 32; s += 128) list[s] = 0;
    __syncthreads();

    const float4* dg = (const float4*)(de + (size_t)doc * DD * EE);

    // ---- Groups 1,2: chunks 0,1 (empty groups when NC is small) ----
    if (NC > 0) load_chunk_gather(sb + 0 * BUFB, dg, list, 0, tid); else commit_group();
    if (NC > 1) load_chunk_gather(sb + 1 * BUFB, dg, list, 1, tid); else commit_group();

    // Wait Q (2 newer groups pending), then preload B fragments.
    asm volatile("cp.async.wait_group 2;" ::: "memory");
    __syncthreads();

    // bq[nt][ks][j] = tf32(Q[n][k]); n = nh*16 + nt*8 + lane/4,
    // k = ks*8 + (lane%4) + j*4.
    const float* qsm = (const float*)(smem + 2 * BUFB);
    uint32_t bq[2][16][2];
    {
        const float* pbase = qsm + (nh * 16 + (lid >> 2)) * RS + (lid & 3);
#pragma unroll
        for (int nt = 0; nt < 2; nt++)
#pragma unroll
            for (int ks = 0; ks < 16; ks++) {
                const float* p = pbase + (nt * 8) * RS + ks * 8;
                bq[nt][ks][0] = to_tf32(p[0]);
                bq[nt][ks][1] = to_tf32(p[4]);
            }
    }
    __syncthreads();                      // Q region free for chunk 2

    // Group 3: chunk 2 into buf2.
    if (NC > 2) load_chunk_gather(sb + 2 * BUFB, dg, list, 2, tid); else commit_group();

    const uint32_t a_lane_off =
        (uint32_t)(mt * 16 + (lid & 15)) * RSB + (uint32_t)(lid >> 4) * 16u;
    const int trow_lane = (lid >> 2);

    float rmax[2][2];
    rmax[0][0] = MASKV; rmax[0][1] = MASKV; rmax[1][0] = MASKV; rmax[1][1] = MASKV;

    // ---- Main loop over compacted chunks; one commit per iteration keeps
    //      group accounting constant (wait_group 2 == chunk c landed). ----
    unsigned bi = 0;
    for (int c = 0; c < NC; ++c) {
        const int slot = c * CH + mt * 16 + trow_lane;
        const int dok0 = slot < V;
        const int dok1 = slot + 8 < V;

        asm volatile("cp.async.wait_group 2;" ::: "memory");
        __syncthreads();

        compute_chunk(sb + bi * BUFB, a_lane_off, bq, dok0, dok1, rmax);

        __syncthreads();                  // all warps done reading buf bi
        if (c + 3 < NC) load_chunk_gather(sb + bi * BUFB, dg, list, c + 3, tid);
        else            commit_group();
        bi = (bi == 2) ? 0 : bi + 1;
    }

    // Butterfly max over token rows (lane bits 2..4).
#pragma unroll
    for (int nt = 0; nt < 2; nt++)
#pragma unroll
        for (int j = 0; j < 2; j++) {
            float x = rmax[nt][j];
#pragma unroll
            for (int o = 4; o < 32; o <<= 1)
                x = fmaxf(x, __shfl_xor_sync(0xFFFFFFFFu, x, o));
            rmax[nt][j] = x;
        }

    // Warp covers 16 q-cols: local col = nt*8 + (lane&3)*2 + j.
    if (lid < 4) {
#pragma unroll
        for (int nt = 0; nt < 2; nt++)
#pragma unroll
            for (int j = 0; j < 2; j++)
                red[wid * 16 + nt * 8 + lid * 2 + j] = rmax[nt][j];
    }
    __syncthreads();

    // Final: combine the two m-tile warps per n-half, q-mask, sum over q.
    if (tid < 32) {
        const int h = tid >> 4;
        const int i = tid & 15;
        float m = fmaxf(red[(h * 2) * 16 + i], red[(h * 2 + 1) * 16 + i]);
        const int qok = qm[b * QQ + tid];
        float contrib = (qok != 0 && m != MASKV) ? m : 0.0f;
#pragma unroll
        for (int o = 16; o; o >>= 1)
            contrib += __shfl_xor_sync(0xFFFFFFFFu, contrib, o);
        if (tid == 0) out[doc] = contrib;
    }
}

extern "C" void kernel_launch(void* const* d_in, const int* in_sizes, int n_in,
                              void* d_out, int out_size) {
    (void)in_sizes; (void)n_in; (void)out_size;
    cudaFuncSetAttribute(mvr_maxsim_kernel,
                         cudaFuncAttributeMaxDynamicSharedMemorySize, SMEM_BYTES);
    mvr_maxsim_kernel<<<BB * NN, 128, SMEM_BYTES>>>(
        (const float*)d_in[0], (const int*)d_in[1],
        (const float*)d_in[2], (const int*)d_in[3],
        (float*)d_out);
}